// round 9
// baseline (speedup 1.0000x reference)
#include <cuda_runtime.h>
#include <cuda_bf16.h>
#include <cstdint>

#define NN 50000
#define NE 1000000
#define SA 400            // node kernels: [hi|lo|hi] stride (bytes)
#define SAE 272           // edge A: [hi|lo] stride (17x16B, odd -> conflict-free ldmatrix)
#define SB 400            // B stride (bytes), layout [hi|hi|lo]
#define KSPLIT 192
#define NSTEP 12

// ---------------- device scratch (allocation-free rule) ----------------
__device__ __align__(16) float g_P[NN * 64];
__device__ __align__(16) float g_S[NN * 64];
__device__ __align__(16) float g_den[NN];
__device__ __align__(16) __nv_bfloat16 g_Wva_s[64 * KSPLIT];
__device__ __align__(16) __nv_bfloat16 g_Waa_s[64 * KSPLIT];
__device__ __align__(16) __nv_bfloat16 g_Wav_s[64 * KSPLIT];
__device__ __align__(16) __nv_bfloat16 g_Wvv_s[64 * KSPLIT];

// ---------------- helpers ----------------
__device__ __forceinline__ uint32_t smem_u32(const void* p) {
    uint32_t a;
    asm("{ .reg .u64 t; cvta.to.shared.u64 t, %1; cvt.u32.u64 %0, t; }"
        : "=r"(a) : "l"(p));
    return a;
}
__device__ __forceinline__ void ldm_x4(uint32_t* r, uint32_t addr) {
    asm volatile("ldmatrix.sync.aligned.m8n8.x4.shared.b16 {%0,%1,%2,%3}, [%4];"
                 : "=r"(r[0]), "=r"(r[1]), "=r"(r[2]), "=r"(r[3]) : "r"(addr));
}
__device__ __forceinline__ void mma16816(float* c, const uint32_t* a,
                                         uint32_t b0, uint32_t b1) {
    asm volatile(
        "mma.sync.aligned.m16n8k16.row.col.f32.bf16.bf16.f32 "
        "{%0,%1,%2,%3}, {%4,%5,%6,%7}, {%8,%9}, {%0,%1,%2,%3};"
        : "+f"(c[0]), "+f"(c[1]), "+f"(c[2]), "+f"(c[3])
        : "r"(a[0]), "r"(a[1]), "r"(a[2]), "r"(a[3]), "r"(b0), "r"(b1));
}
__device__ __forceinline__ uint32_t pack_bf2(__nv_bfloat16 a, __nv_bfloat16 b) {
    uint32_t ua = __bfloat16_as_ushort(a), ub = __bfloat16_as_ushort(b);
    return ua | (ub << 16);
}

// float4 -> [hi | lo | hi] (node kernels, stride SA)
__device__ __forceinline__ void store_hl3(char* Arow, int k, float4 f) {
    __nv_bfloat16 h0 = __float2bfloat16_rn(f.x), h1 = __float2bfloat16_rn(f.y);
    __nv_bfloat16 h2 = __float2bfloat16_rn(f.z), h3 = __float2bfloat16_rn(f.w);
    float l0 = f.x - __bfloat162float(h0), l1 = f.y - __bfloat162float(h1);
    float l2 = f.z - __bfloat162float(h2), l3 = f.w - __bfloat162float(h3);
    uint2 hv = make_uint2(pack_bf2(h0, h1), pack_bf2(h2, h3));
    uint2 lv = make_uint2(
        pack_bf2(__float2bfloat16_rn(l0), __float2bfloat16_rn(l1)),
        pack_bf2(__float2bfloat16_rn(l2), __float2bfloat16_rn(l3)));
    *(uint2*)(Arow + k * 2)       = hv;
    *(uint2*)(Arow + 128 + k * 2) = lv;
    *(uint2*)(Arow + 256 + k * 2) = hv;
}

// float4 -> [hi | lo] (edge kernel, stride SAE)
__device__ __forceinline__ void store_hl2(char* Arow, int k, float4 f) {
    __nv_bfloat16 h0 = __float2bfloat16_rn(f.x), h1 = __float2bfloat16_rn(f.y);
    __nv_bfloat16 h2 = __float2bfloat16_rn(f.z), h3 = __float2bfloat16_rn(f.w);
    float l0 = f.x - __bfloat162float(h0), l1 = f.y - __bfloat162float(h1);
    float l2 = f.z - __bfloat162float(h2), l3 = f.w - __bfloat162float(h3);
    uint2 hv = make_uint2(pack_bf2(h0, h1), pack_bf2(h2, h3));
    uint2 lv = make_uint2(
        pack_bf2(__float2bfloat16_rn(l0), __float2bfloat16_rn(l1)),
        pack_bf2(__float2bfloat16_rn(l2), __float2bfloat16_rn(l3)));
    *(uint2*)(Arow + k * 2)       = hv;   // [0,64): hi
    *(uint2*)(Arow + 128 + k * 2) = lv;   // [64,128): lo
}

// node-kernel core: 16-row tile, A [hi|lo|hi] @SA, B [hi|hi|lo] @SB, K=192
__device__ __forceinline__ void gemm_k192(uint32_t aB, uint32_t bB, int m0,
                                          int lane, float c[8][4]) {
#pragma unroll
    for (int i = 0; i < 8; i++)
        c[i][0] = c[i][1] = c[i][2] = c[i][3] = 0.f;
    uint32_t aRow = aB + (uint32_t)(m0 + (lane & 15)) * SA + ((lane >> 4) << 4);
    uint32_t bRow = bB + (uint32_t)(lane & 15) * SB + ((lane >> 4) << 4);
#pragma unroll
    for (int ks = 0; ks < NSTEP; ks++) {
        uint32_t a[4];
        ldm_x4(a, aRow + ks * 32);
#pragma unroll
        for (int np = 0; np < 4; np++) {
            uint32_t b[4];
            ldm_x4(b, bRow + np * 16 * SB + ks * 32);
            mma16816(c[np * 2],     a, b[0], b[2]);
            mma16816(c[np * 2 + 1], a, b[1], b[3]);
        }
    }
}

// edge core: 32-row tile, A [hi|lo] @SAE, B [hi|hi|lo] @SB.
// piece1: K=128 (A hi+lo x B hi+hi); piece2: K=64 (A hi x B lo)
__device__ __forceinline__ void gemm32_split(uint32_t aB, uint32_t bB, int m0,
                                             int lane, float c[2][8][4]) {
#pragma unroll
    for (int s = 0; s < 2; s++)
#pragma unroll
        for (int i = 0; i < 8; i++)
            c[s][i][0] = c[s][i][1] = c[s][i][2] = c[s][i][3] = 0.f;
    uint32_t aR0 = aB + (uint32_t)(m0 + (lane & 15)) * SAE + ((lane >> 4) << 4);
    uint32_t aR1 = aR0 + 16 * SAE;
    uint32_t bR  = bB + (uint32_t)(lane & 15) * SB + ((lane >> 4) << 4);
#pragma unroll
    for (int ks = 0; ks < 8; ks++) {          // piece 1
        uint32_t a0[4], a1[4];
        ldm_x4(a0, aR0 + ks * 32);
        ldm_x4(a1, aR1 + ks * 32);
#pragma unroll
        for (int np = 0; np < 4; np++) {
            uint32_t b[4];
            ldm_x4(b, bR + np * 16 * SB + ks * 32);
            mma16816(c[0][np * 2],     a0, b[0], b[2]);
            mma16816(c[0][np * 2 + 1], a0, b[1], b[3]);
            mma16816(c[1][np * 2],     a1, b[0], b[2]);
            mma16816(c[1][np * 2 + 1], a1, b[1], b[3]);
        }
    }
#pragma unroll
    for (int ks = 0; ks < 4; ks++) {          // piece 2: A hi x B lo
        uint32_t a0[4], a1[4];
        ldm_x4(a0, aR0 + ks * 32);
        ldm_x4(a1, aR1 + ks * 32);
#pragma unroll
        for (int np = 0; np < 4; np++) {
            uint32_t b[4];
            ldm_x4(b, bR + np * 16 * SB + 256 + ks * 32);
            mma16816(c[0][np * 2],     a0, b[0], b[2]);
            mma16816(c[0][np * 2 + 1], a0, b[1], b[3]);
            mma16816(c[1][np * 2],     a1, b[0], b[2]);
            mma16816(c[1][np * 2 + 1], a1, b[1], b[3]);
        }
    }
}

// ---------------- wprep: B = [hi | hi | lo], 4 blocks ----------------
__global__ void wprep_kernel(const float* __restrict__ Wva,
                             const float* __restrict__ Waa,
                             const float* __restrict__ Wav,
                             const float* __restrict__ Wvv) {
    const float* src[4] = {Wva, Waa, Wav, Wvv};
    __nv_bfloat16* dst[4] = {g_Wva_s, g_Waa_s, g_Wav_s, g_Wvv_s};
    int m = blockIdx.x;
    const float* W = src[m];
    __nv_bfloat16* D = dst[m];
    for (int i = threadIdx.x; i < 4096; i += 256) {
        int j = i >> 6, k = i & 63;
        float f = W[i];
        __nv_bfloat16 h = __float2bfloat16_rn(f);
        __nv_bfloat16 l = __float2bfloat16_rn(f - __bfloat162float(h));
        D[j * KSPLIT + k]       = h;
        D[j * KSPLIT + 64 + k]  = h;
        D[j * KSPLIT + 128 + k] = l;
    }
}

// ---------------- K0: P = x_v @ W_av^T ; zero S, den ----------------
__global__ void __launch_bounds__(256) node_pre_kernel(const float* __restrict__ x_v)
{
    extern __shared__ char sm[];
    char* A = sm;              // 128*400 = 51200
    char* B = sm + 51200;      // 64*400  = 25600
    int tid = threadIdx.x;
    int nb = blockIdx.x * 128;

    for (int i = tid; i < 64 * 24; i += 256) {
        int r = i / 24, c4 = i % 24;
        ((uint4*)(B + r * SB))[c4] = ((const uint4*)g_Wav_s)[i];
    }
    {
        int r = tid >> 1, ko = (tid & 1) * 32;
        int n = nb + r;
        char* Arow = A + r * SA;
        if (n < NN) {
            const float4* gx = (const float4*)(x_v + (size_t)n * 64 + ko);
#pragma unroll
            for (int i = 0; i < 8; i++) store_hl3(Arow, ko + i * 4, gx[i]);
        } else {
            uint2 z = make_uint2(0, 0);
#pragma unroll
            for (int i = 0; i < 8; i++) {
                int k = ko + i * 4;
                *(uint2*)(Arow + k * 2) = z;
                *(uint2*)(Arow + 128 + k * 2) = z;
                *(uint2*)(Arow + 256 + k * 2) = z;
            }
        }
    }
    float4 z4 = make_float4(0.f, 0.f, 0.f, 0.f);
    for (int i = tid; i < 2048; i += 256) {
        int n = nb + (i >> 4);
        if (n < NN) ((float4*)(g_S + (size_t)n * 64))[i & 15] = z4;
    }
    if (tid < 128 && nb + tid < NN) g_den[nb + tid] = 0.f;
    __syncthreads();

    int lane = tid & 31, m0 = (tid >> 5) * 16;
    float c[8][4];
    gemm_k192(smem_u32(A), smem_u32(B), m0, lane, c);

    int r0 = m0 + (lane >> 2), r1 = r0 + 8;
    int col0 = (lane & 3) * 2;
    int n0 = nb + r0, n1 = nb + r1;
#pragma unroll
    for (int nt = 0; nt < 8; nt++) {
        int col = nt * 8 + col0;
        if (n0 < NN) *(float2*)(g_P + (size_t)n0 * 64 + col) = make_float2(c[nt][0], c[nt][1]);
        if (n1 < NN) *(float2*)(g_P + (size_t)n1 * 64 + col) = make_float2(c[nt][2], c[nt][3]);
    }
}

// ---------------- K1: edge kernel — warp-specialized dual GEMM ----------------
// smem: A 0..34816 | Bva ..60416 | Baa ..86016 | slog | ssrc | sdst | sbias
__global__ void __launch_bounds__(256, 2) edge_kernel(
    const float* __restrict__ x_a, const int* __restrict__ arc,
    const float* __restrict__ W_att, const float* __restrict__ b_att,
    const float* __restrict__ b_aa, float* __restrict__ out_a)
{
    extern __shared__ char sm[];
    char*  A    = sm;                       // 128*272 = 34816
    char*  Bva  = sm + 34816;               // 25600
    char*  Baa  = sm + 60416;               // 25600
    float* slog = (float*)(sm + 86016);     // 128
    int*   ssrc = (int*)(sm + 86528);       // 128
    int*   sdst = (int*)(sm + 87040);       // 128
    float* sbias= (float*)(sm + 87552);     // 64

    int tid = threadIdx.x;
    int eb = blockIdx.x * 128;

    // phase 1: weights -> smem; indices; bias; logit init
    for (int i = tid; i < 64 * 24; i += 256) {
        int r = i / 24, c4 = i % 24;
        ((uint4*)(Bva + r * SB))[c4] = ((const uint4*)g_Wva_s)[i];
        ((uint4*)(Baa + r * SB))[c4] = ((const uint4*)g_Waa_s)[i];
    }
    float battv = __ldg(b_att);
    if (tid < 128) {
        int e = eb + tid;
        slog[tid] = (e < NE) ? battv : -1e30f;
        ssrc[tid] = (e < NE) ? __ldg(arc + e) : 0;
    } else {
        int r = tid - 128, e = eb + r;
        sdst[r] = (e < NE) ? __ldg(arc + NE + e) : 0;
        if (tid < 192) sbias[tid - 128] = __ldg(b_aa + (tid - 128));
    }
    __syncthreads();

    // phase 2: A tile convert + logit partial dot (2 threads per row)
    {
        int r = tid >> 1, ko = (tid & 1) * 32;
        int e = eb + r;
        char* Arow = A + r * SAE;
        if (e < NE) {
            const float4* gx = (const float4*)(x_a + (size_t)e * 64 + ko);
            const float4* gw = (const float4*)(W_att + ko);
            float part = 0.f;
#pragma unroll
            for (int i = 0; i < 8; i++) {
                float4 f = gx[i];
                float4 wv = __ldg(gw + i);
                part += f.x * wv.x + f.y * wv.y + f.z * wv.z + f.w * wv.w;
                store_hl2(Arow, ko + i * 4, f);
            }
            atomicAdd(&slog[r], part);
        } else {
            uint2 z = make_uint2(0, 0);
#pragma unroll
            for (int i = 0; i < 8; i++) {
                int k = ko + i * 4;
                *(uint2*)(Arow + k * 2) = z;
                *(uint2*)(Arow + 128 + k * 2) = z;
            }
        }
    }
    __syncthreads();

    // phase 3: w = exp(logit); den atomics
    if (tid < 128) {
        int e = eb + tid;
        float w = __expf(slog[tid]);
        slog[tid] = w;
        if (e < NE) atomicAdd(&g_den[sdst[tid]], w);
    }
    __syncthreads();

    int lane = tid & 31, wid = tid >> 5;
    uint32_t aB = smem_u32(A);
    float c[2][8][4];

    if (wid < 4) {
        // ---- GEMM 1 (warps 0-3, 32 rows each): S[dst] += w * (x_a @ W_va^T) ----
        int m0 = wid * 32;
        gemm32_split(aB, smem_u32(Bva), m0, lane, c);
        int col0 = (lane & 3) * 2;
#pragma unroll
        for (int s = 0; s < 2; s++) {
            int r0 = m0 + s * 16 + (lane >> 2), r1 = r0 + 8;
            float w0 = slog[r0], w1 = slog[r1];
            float* S0 = g_S + (size_t)sdst[r0] * 64;
            float* S1 = g_S + (size_t)sdst[r1] * 64;
#pragma unroll
            for (int nt = 0; nt < 8; nt++) {
                int col = nt * 8 + col0;
                asm volatile("red.global.add.v2.f32 [%0], {%1,%2};"
                             :: "l"(S0 + col), "f"(c[s][nt][0] * w0), "f"(c[s][nt][1] * w0)
                             : "memory");
                asm volatile("red.global.add.v2.f32 [%0], {%1,%2};"
                             :: "l"(S1 + col), "f"(c[s][nt][2] * w1), "f"(c[s][nt][3] * w1)
                             : "memory");
            }
        }
    } else {
        // ---- GEMM 2 (warps 4-7, 32 rows each): out_a = x_a@W_aa^T + b + P[src]+P[dst] ----
        int m0 = (wid - 4) * 32;
        gemm32_split(aB, smem_u32(Baa), m0, lane, c);
        int col0 = (lane & 3) * 2;
#pragma unroll
        for (int s = 0; s < 2; s++) {
            int r0 = m0 + s * 16 + (lane >> 2), r1 = r0 + 8;
            int e0 = eb + r0, e1 = eb + r1;
            const float* Ps0 = g_P + (size_t)ssrc[r0] * 64;
            const float* Pd0 = g_P + (size_t)sdst[r0] * 64;
            const float* Ps1 = g_P + (size_t)ssrc[r1] * 64;
            const float* Pd1 = g_P + (size_t)sdst[r1] * 64;
#pragma unroll
            for (int nt = 0; nt < 8; nt++) {
                int col = nt * 8 + col0;
                if (e0 < NE) {
                    float2 ps = *(const float2*)(Ps0 + col);
                    float2 pd = *(const float2*)(Pd0 + col);
                    *(float2*)(out_a + (size_t)e0 * 64 + col) =
                        make_float2(c[s][nt][0] + sbias[col] + ps.x + pd.x,
                                    c[s][nt][1] + sbias[col + 1] + ps.y + pd.y);
                }
                if (e1 < NE) {
                    float2 ps = *(const float2*)(Ps1 + col);
                    float2 pd = *(const float2*)(Pd1 + col);
                    *(float2*)(out_a + (size_t)e1 * 64 + col) =
                        make_float2(c[s][nt][2] + sbias[col] + ps.x + pd.x,
                                    c[s][nt][3] + sbias[col + 1] + ps.y + pd.y);
                }
            }
        }
    }
}

// ---------------- K2: h_v = x_v @ W_vv^T + b_vv + S/den ----------------
__global__ void __launch_bounds__(256) node_post_kernel(
    const float* __restrict__ x_v, const float* __restrict__ b_vv,
    float* __restrict__ out_v)
{
    extern __shared__ char sm[];
    char*  A  = sm;                  // 51200
    char*  B  = sm + 51200;          // 25600
    float* sb = (float*)(sm + 76800);// 64
    int tid = threadIdx.x;
    int nb = blockIdx.x * 128;

    for (int i = tid; i < 64 * 24; i += 256) {
        int r = i / 24, c4 = i % 24;
        ((uint4*)(B + r * SB))[c4] = ((const uint4*)g_Wvv_s)[i];
    }
    if (tid < 64) sb[tid] = __ldg(b_vv + tid);
    {
        int r = tid >> 1, ko = (tid & 1) * 32;
        int n = nb + r;
        char* Arow = A + r * SA;
        if (n < NN) {
            const float4* gx = (const float4*)(x_v + (size_t)n * 64 + ko);
#pragma unroll
            for (int i = 0; i < 8; i++) store_hl3(Arow, ko + i * 4, gx[i]);
        } else {
            uint2 z = make_uint2(0, 0);
#pragma unroll
            for (int i = 0; i < 8; i++) {
                int k = ko + i * 4;
                *(uint2*)(Arow + k * 2) = z;
                *(uint2*)(Arow + 128 + k * 2) = z;
                *(uint2*)(Arow + 256 + k * 2) = z;
            }
        }
    }
    __syncthreads();

    int lane = tid & 31, m0 = (tid >> 5) * 16;
    float c[8][4];
    gemm_k192(smem_u32(A), smem_u32(B), m0, lane, c);

    int r0 = m0 + (lane >> 2), r1 = r0 + 8;
    int col0 = (lane & 3) * 2;
    int n0 = nb + r0, n1 = nb + r1;
    float inv0 = 0.f, inv1 = 0.f;
    if (n0 < NN) { float d = g_den[n0]; inv0 = (d > 0.f) ? 1.f / d : 0.f; }
    if (n1 < NN) { float d = g_den[n1]; inv1 = (d > 0.f) ? 1.f / d : 0.f; }
#pragma unroll
    for (int nt = 0; nt < 8; nt++) {
        int col = nt * 8 + col0;
        if (n0 < NN) {
            float2 s = *(const float2*)(g_S + (size_t)n0 * 64 + col);
            *(float2*)(out_v + (size_t)n0 * 64 + col) =
                make_float2(c[nt][0] + sb[col] + s.x * inv0,
                            c[nt][1] + sb[col + 1] + s.y * inv0);
        }
        if (n1 < NN) {
            float2 s = *(const float2*)(g_S + (size_t)n1 * 64 + col);
            *(float2*)(out_v + (size_t)n1 * 64 + col) =
                make_float2(c[nt][2] + sb[col] + s.x * inv1,
                            c[nt][3] + sb[col + 1] + s.y * inv1);
        }
    }
}

// ---------------------------------------------------------------------------
extern "C" void kernel_launch(void* const* d_in, const int* in_sizes, int n_in,
                              void* d_out, int out_size)
{
    const float* x_v   = (const float*)d_in[0];
    const float* x_a   = (const float*)d_in[1];
    const int*   arc   = (const int*)  d_in[2];
    const float* W_vv  = (const float*)d_in[3];
    const float* b_vv  = (const float*)d_in[4];
    const float* W_va  = (const float*)d_in[5];
    const float* W_att = (const float*)d_in[6];
    const float* b_att = (const float*)d_in[7];
    const float* W_aa  = (const float*)d_in[8];
    const float* b_aa  = (const float*)d_in[9];
    const float* W_av  = (const float*)d_in[10];

    float* out_v = (float*)d_out;
    float* out_a = (float*)d_out + (size_t)NN * 64;

    const int EDGE_SMEM = 87808;
    const int NODE_SMEM = 77312;
    cudaFuncSetAttribute(edge_kernel, cudaFuncAttributeMaxDynamicSharedMemorySize, EDGE_SMEM);
    cudaFuncSetAttribute(node_pre_kernel, cudaFuncAttributeMaxDynamicSharedMemorySize, NODE_SMEM);
    cudaFuncSetAttribute(node_post_kernel, cudaFuncAttributeMaxDynamicSharedMemorySize, NODE_SMEM);

    wprep_kernel<<<4, 256>>>(W_va, W_aa, W_av, W_vv);
    node_pre_kernel<<<(NN + 127) / 128, 256, NODE_SMEM>>>(x_v);
    edge_kernel<<<(NE + 127) / 128, 256, EDGE_SMEM>>>(x_a, arc, W_att, b_att,
                                                      b_aa, out_a);
    node_post_kernel<<<(NN + 127) / 128, 256, NODE_SMEM>>>(x_v, b_vv, out_v);
}

// round 11
// speedup vs baseline: 1.3023x; 1.3023x over previous
#include <cuda_runtime.h>
#include <cuda_bf16.h>
#include <cstdint>

#define NN 50000
#define NE 1000000
#define SA 400            // A stride for [hi|lo|hi] (25x16B, odd -> conflict-free ldmatrix)
#define SAE 272           // edge A: [hi|lo] stride (17x16B)
#define SB 400            // B stride, layout [hi|hi|lo]
#define KSPLIT 192
#define NSTEP 12

// ---------------- device scratch (allocation-free rule) ----------------
__device__ __align__(16) float g_P[NN * 64];     // x_v @ W_av^T
__device__ __align__(16) float g_T[NN * 64];     // sum_e w_e * x_a_e  (input space!)
__device__ __align__(16) float g_den[NN];
__device__ __align__(16) __nv_bfloat16 g_Wva_s[64 * KSPLIT];
__device__ __align__(16) __nv_bfloat16 g_Waa_s[64 * KSPLIT];
__device__ __align__(16) __nv_bfloat16 g_Wav_s[64 * KSPLIT];
__device__ __align__(16) __nv_bfloat16 g_Wvv_s[64 * KSPLIT];

// ---------------- helpers ----------------
__device__ __forceinline__ uint32_t smem_u32(const void* p) {
    uint32_t a;
    asm("{ .reg .u64 t; cvta.to.shared.u64 t, %1; cvt.u32.u64 %0, t; }"
        : "=r"(a) : "l"(p));
    return a;
}
__device__ __forceinline__ void ldm_x4(uint32_t* r, uint32_t addr) {
    asm volatile("ldmatrix.sync.aligned.m8n8.x4.shared.b16 {%0,%1,%2,%3}, [%4];"
                 : "=r"(r[0]), "=r"(r[1]), "=r"(r[2]), "=r"(r[3]) : "r"(addr));
}
__device__ __forceinline__ void mma16816(float* c, const uint32_t* a,
                                         uint32_t b0, uint32_t b1) {
    asm volatile(
        "mma.sync.aligned.m16n8k16.row.col.f32.bf16.bf16.f32 "
        "{%0,%1,%2,%3}, {%4,%5,%6,%7}, {%8,%9}, {%0,%1,%2,%3};"
        : "+f"(c[0]), "+f"(c[1]), "+f"(c[2]), "+f"(c[3])
        : "r"(a[0]), "r"(a[1]), "r"(a[2]), "r"(a[3]), "r"(b0), "r"(b1));
}
__device__ __forceinline__ uint32_t pack_bf2(__nv_bfloat16 a, __nv_bfloat16 b) {
    uint32_t ua = __bfloat16_as_ushort(a), ub = __bfloat16_as_ushort(b);
    return ua | (ub << 16);
}

// float4 -> [hi | lo | hi] (stride SA)
__device__ __forceinline__ void store_hl3(char* Arow, int k, float4 f) {
    __nv_bfloat16 h0 = __float2bfloat16_rn(f.x), h1 = __float2bfloat16_rn(f.y);
    __nv_bfloat16 h2 = __float2bfloat16_rn(f.z), h3 = __float2bfloat16_rn(f.w);
    float l0 = f.x - __bfloat162float(h0), l1 = f.y - __bfloat162float(h1);
    float l2 = f.z - __bfloat162float(h2), l3 = f.w - __bfloat162float(h3);
    uint2 hv = make_uint2(pack_bf2(h0, h1), pack_bf2(h2, h3));
    uint2 lv = make_uint2(
        pack_bf2(__float2bfloat16_rn(l0), __float2bfloat16_rn(l1)),
        pack_bf2(__float2bfloat16_rn(l2), __float2bfloat16_rn(l3)));
    *(uint2*)(Arow + k * 2)       = hv;
    *(uint2*)(Arow + 128 + k * 2) = lv;
    *(uint2*)(Arow + 256 + k * 2) = hv;
}

// float4 -> [hi | lo] (edge kernel, stride SAE)
__device__ __forceinline__ void store_hl2(char* Arow, int k, float4 f) {
    __nv_bfloat16 h0 = __float2bfloat16_rn(f.x), h1 = __float2bfloat16_rn(f.y);
    __nv_bfloat16 h2 = __float2bfloat16_rn(f.z), h3 = __float2bfloat16_rn(f.w);
    float l0 = f.x - __bfloat162float(h0), l1 = f.y - __bfloat162float(h1);
    float l2 = f.z - __bfloat162float(h2), l3 = f.w - __bfloat162float(h3);
    uint2 hv = make_uint2(pack_bf2(h0, h1), pack_bf2(h2, h3));
    uint2 lv = make_uint2(
        pack_bf2(__float2bfloat16_rn(l0), __float2bfloat16_rn(l1)),
        pack_bf2(__float2bfloat16_rn(l2), __float2bfloat16_rn(l3)));
    *(uint2*)(Arow + k * 2)       = hv;
    *(uint2*)(Arow + 128 + k * 2) = lv;
}

// accumulating core: 16-row tile, A [hi|lo|hi] @SA, B [hi|hi|lo] @SB, K=192
__device__ __forceinline__ void gemm_k192_acc(uint32_t aB, uint32_t bB, int m0,
                                              int lane, float c[8][4]) {
    uint32_t aRow = aB + (uint32_t)(m0 + (lane & 15)) * SA + ((lane >> 4) << 4);
    uint32_t bRow = bB + (uint32_t)(lane & 15) * SB + ((lane >> 4) << 4);
#pragma unroll
    for (int ks = 0; ks < NSTEP; ks++) {
        uint32_t a[4];
        ldm_x4(a, aRow + ks * 32);
#pragma unroll
        for (int np = 0; np < 4; np++) {
            uint32_t b[4];
            ldm_x4(b, bRow + np * 16 * SB + ks * 32);
            mma16816(c[np * 2],     a, b[0], b[2]);
            mma16816(c[np * 2 + 1], a, b[1], b[3]);
        }
    }
}

// edge core: 16-row tile, A [hi|lo] @SAE, B [hi|hi|lo] @SB.
// piece1: K=128 (A hi+lo x B hi+hi); piece2: K=64 (A hi x B lo)
__device__ __forceinline__ void gemm_edge(uint32_t aB, uint32_t bB, int m0,
                                          int lane, float c[8][4]) {
#pragma unroll
    for (int i = 0; i < 8; i++)
        c[i][0] = c[i][1] = c[i][2] = c[i][3] = 0.f;
    uint32_t aRow = aB + (uint32_t)(m0 + (lane & 15)) * SAE + ((lane >> 4) << 4);
    uint32_t bRow = bB + (uint32_t)(lane & 15) * SB + ((lane >> 4) << 4);
#pragma unroll
    for (int ks = 0; ks < 8; ks++) {
        uint32_t a[4];
        ldm_x4(a, aRow + ks * 32);
#pragma unroll
        for (int np = 0; np < 4; np++) {
            uint32_t b[4];
            ldm_x4(b, bRow + np * 16 * SB + ks * 32);
            mma16816(c[np * 2],     a, b[0], b[2]);
            mma16816(c[np * 2 + 1], a, b[1], b[3]);
        }
    }
#pragma unroll
    for (int ks = 0; ks < 4; ks++) {          // A hi x B lo
        uint32_t a[4];
        ldm_x4(a, aRow + ks * 32);
#pragma unroll
        for (int np = 0; np < 4; np++) {
            uint32_t b[4];
            ldm_x4(b, bRow + np * 16 * SB + 256 + ks * 32);
            mma16816(c[np * 2],     a, b[0], b[2]);
            mma16816(c[np * 2 + 1], a, b[1], b[3]);
        }
    }
}

// ---------------- wprep: B = [hi | hi | lo] ----------------
__global__ void wprep_kernel(const float* __restrict__ Wva,
                             const float* __restrict__ Waa,
                             const float* __restrict__ Wav,
                             const float* __restrict__ Wvv) {
    const float* src[4] = {Wva, Waa, Wav, Wvv};
    __nv_bfloat16* dst[4] = {g_Wva_s, g_Waa_s, g_Wav_s, g_Wvv_s};
    int m = blockIdx.x;
    const float* W = src[m];
    __nv_bfloat16* D = dst[m];
    for (int i = threadIdx.x; i < 4096; i += 256) {
        int j = i >> 6, k = i & 63;
        float f = W[i];
        __nv_bfloat16 h = __float2bfloat16_rn(f);
        __nv_bfloat16 l = __float2bfloat16_rn(f - __bfloat162float(h));
        D[j * KSPLIT + k]       = h;
        D[j * KSPLIT + 64 + k]  = h;
        D[j * KSPLIT + 128 + k] = l;
    }
}

// ---------------- K0: P = x_v @ W_av^T ; zero T, den ----------------
__global__ void __launch_bounds__(256) node_pre_kernel(const float* __restrict__ x_v)
{
    extern __shared__ char sm[];
    char* A = sm;              // 128*400 = 51200
    char* B = sm + 51200;      // 25600
    int tid = threadIdx.x;
    int nb = blockIdx.x * 128;

    for (int i = tid; i < 64 * 24; i += 256) {
        int r = i / 24, c4 = i % 24;
        ((uint4*)(B + r * SB))[c4] = ((const uint4*)g_Wav_s)[i];
    }
    {
        int r = tid >> 1, ko = (tid & 1) * 32;
        int n = nb + r;
        char* Arow = A + r * SA;
        if (n < NN) {
            const float4* gx = (const float4*)(x_v + (size_t)n * 64 + ko);
#pragma unroll
            for (int i = 0; i < 8; i++) store_hl3(Arow, ko + i * 4, gx[i]);
        } else {
            uint2 z = make_uint2(0, 0);
#pragma unroll
            for (int i = 0; i < 8; i++) {
                int k = ko + i * 4;
                *(uint2*)(Arow + k * 2) = z;
                *(uint2*)(Arow + 128 + k * 2) = z;
                *(uint2*)(Arow + 256 + k * 2) = z;
            }
        }
    }
    float4 z4 = make_float4(0.f, 0.f, 0.f, 0.f);
    for (int i = tid; i < 2048; i += 256) {
        int n = nb + (i >> 4);
        if (n < NN) ((float4*)(g_T + (size_t)n * 64))[i & 15] = z4;
    }
    if (tid < 128 && nb + tid < NN) g_den[nb + tid] = 0.f;
    __syncthreads();

    int lane = tid & 31, m0 = (tid >> 5) * 16;
    float c[8][4];
#pragma unroll
    for (int i = 0; i < 8; i++) c[i][0] = c[i][1] = c[i][2] = c[i][3] = 0.f;
    gemm_k192_acc(smem_u32(A), smem_u32(B), m0, lane, c);

    int r0 = m0 + (lane >> 2), r1 = r0 + 8;
    int col0 = (lane & 3) * 2;
    int n0 = nb + r0, n1 = nb + r1;
#pragma unroll
    for (int nt = 0; nt < 8; nt++) {
        int col = nt * 8 + col0;
        if (n0 < NN) *(float2*)(g_P + (size_t)n0 * 64 + col) = make_float2(c[nt][0], c[nt][1]);
        if (n1 < NN) *(float2*)(g_P + (size_t)n1 * 64 + col) = make_float2(c[nt][2], c[nt][3]);
    }
}

// ---------------- K1: edge kernel — single GEMM + raw-input scatter ----------------
// smem: A 0..34816 | Baa ..60416 | slog | ssrc | sdst | sbias   (~62 KB, 2 CTA/SM)
__global__ void __launch_bounds__(256, 2) edge_kernel(
    const float* __restrict__ x_a, const int* __restrict__ arc,
    const float* __restrict__ W_att, const float* __restrict__ b_att,
    const float* __restrict__ b_aa, float* __restrict__ out_a)
{
    extern __shared__ char sm[];
    char*  A    = sm;                       // 128*272 = 34816
    char*  Baa  = sm + 34816;               // 25600
    float* slog = (float*)(sm + 60416);     // 128
    int*   ssrc = (int*)(sm + 60928);       // 128
    int*   sdst = (int*)(sm + 61440);       // 128
    float* sbias= (float*)(sm + 61952);     // 64

    int tid = threadIdx.x;
    int eb = blockIdx.x * 128;

    // phase 1: weights -> smem; indices; bias; logit init
    for (int i = tid; i < 64 * 24; i += 256) {
        int r = i / 24, c4 = i % 24;
        ((uint4*)(Baa + r * SB))[c4] = ((const uint4*)g_Waa_s)[i];
    }
    float battv = __ldg(b_att);
    if (tid < 128) {
        int e = eb + tid;
        slog[tid] = (e < NE) ? battv : -1e30f;
        ssrc[tid] = (e < NE) ? __ldg(arc + e) : 0;
    } else {
        int r = tid - 128, e = eb + r;
        sdst[r] = (e < NE) ? __ldg(arc + NE + e) : 0;
        if (tid < 192) sbias[tid - 128] = __ldg(b_aa + (tid - 128));
    }
    __syncthreads();

    // phase 2: A tile convert + logit partial dot; keep x_a float4s in regs
    int r = tid >> 1, ko = (tid & 1) * 32;
    int er = eb + r;
    float4 xf[8];
    {
        char* Arow = A + r * SAE;
        if (er < NE) {
            const float4* gx = (const float4*)(x_a + (size_t)er * 64 + ko);
            const float4* gw = (const float4*)(W_att + ko);
            float part = 0.f;
#pragma unroll
            for (int i = 0; i < 8; i++) {
                float4 f = gx[i];
                xf[i] = f;
                float4 wv = __ldg(gw + i);
                part += f.x * wv.x + f.y * wv.y + f.z * wv.z + f.w * wv.w;
                store_hl2(Arow, ko + i * 4, f);
            }
            atomicAdd(&slog[r], part);
        } else {
            uint2 z = make_uint2(0, 0);
#pragma unroll
            for (int i = 0; i < 8; i++) {
                int k = ko + i * 4;
                *(uint2*)(Arow + k * 2) = z;
                *(uint2*)(Arow + 128 + k * 2) = z;
            }
        }
    }
    __syncthreads();

    // phase 3: w = exp(logit); den atomic (one thread per edge)
    if (tid < 128) {
        int e = eb + tid;
        float w = __expf(slog[tid]);
        slog[tid] = w;
        if (e < NE) atomicAdd(&g_den[sdst[tid]], w);
    }
    __syncthreads();

    // phase 4: scatter w * x_a into T[dst] straight from registers (red.v4)
    if (er < NE) {
        float w = slog[r];
        float* Td = g_T + (size_t)sdst[r] * 64 + ko;
#pragma unroll
        for (int i = 0; i < 8; i++) {
            float4 f = xf[i];
            asm volatile("red.global.add.v4.f32 [%0], {%1,%2,%3,%4};"
                         :: "l"(Td + i * 4),
                            "f"(f.x * w), "f"(f.y * w), "f"(f.z * w), "f"(f.w * w)
                         : "memory");
        }
    }

    // phase 5: GEMM out_a = x_a @ W_aa^T + b_aa + P[src] + P[dst]
    int lane = tid & 31, m0 = (tid >> 5) * 16;
    float c[8][4];
    gemm_edge(smem_u32(A), smem_u32(Baa), m0, lane, c);
    {
        int r0 = m0 + (lane >> 2), r1 = r0 + 8;
        int col0 = (lane & 3) * 2;
        int e0 = eb + r0, e1 = eb + r1;
        const float* Ps0 = g_P + (size_t)ssrc[r0] * 64;
        const float* Pd0 = g_P + (size_t)sdst[r0] * 64;
        const float* Ps1 = g_P + (size_t)ssrc[r1] * 64;
        const float* Pd1 = g_P + (size_t)sdst[r1] * 64;
#pragma unroll
        for (int nt = 0; nt < 8; nt++) {
            int col = nt * 8 + col0;
            if (e0 < NE) {
                float2 ps = *(const float2*)(Ps0 + col);
                float2 pd = *(const float2*)(Pd0 + col);
                *(float2*)(out_a + (size_t)e0 * 64 + col) =
                    make_float2(c[nt][0] + sbias[col] + ps.x + pd.x,
                                c[nt][1] + sbias[col + 1] + ps.y + pd.y);
            }
            if (e1 < NE) {
                float2 ps = *(const float2*)(Ps1 + col);
                float2 pd = *(const float2*)(Pd1 + col);
                *(float2*)(out_a + (size_t)e1 * 64 + col) =
                    make_float2(c[nt][2] + sbias[col] + ps.x + pd.x,
                                c[nt][3] + sbias[col + 1] + ps.y + pd.y);
            }
        }
    }
}

// ---------------- K2: h_v = x_v @ W_vv^T + b_vv + (T/den) @ W_va^T ----------------
__global__ void __launch_bounds__(256) node_post_kernel(
    const float* __restrict__ x_v, const float* __restrict__ b_vv,
    float* __restrict__ out_v)
{
    extern __shared__ char sm[];
    char*  Axv = sm;                    // 51200
    char*  At  = sm + 51200;            // 51200
    char*  Bvv = sm + 102400;           // 25600
    char*  Bva = sm + 128000;           // 25600
    float* sb  = (float*)(sm + 153600); // 64
    int tid = threadIdx.x;
    int nb = blockIdx.x * 128;

    for (int i = tid; i < 64 * 24; i += 256) {
        int r = i / 24, c4 = i % 24;
        ((uint4*)(Bvv + r * SB))[c4] = ((const uint4*)g_Wvv_s)[i];
        ((uint4*)(Bva + r * SB))[c4] = ((const uint4*)g_Wva_s)[i];
    }
    if (tid < 64) sb[tid] = __ldg(b_vv + tid);
    {
        int r = tid >> 1, ko = (tid & 1) * 32;
        int n = nb + r;
        char* Ax = Axv + r * SA;
        char* Atr = At + r * SA;
        if (n < NN) {
            float d = g_den[n];
            float inv = (d > 0.f) ? 1.f / d : 0.f;
            const float4* gx = (const float4*)(x_v + (size_t)n * 64 + ko);
            const float4* gt = (const float4*)(g_T + (size_t)n * 64 + ko);
#pragma unroll
            for (int i = 0; i < 8; i++) {
                store_hl3(Ax, ko + i * 4, gx[i]);
                float4 t = gt[i];
                store_hl3(Atr, ko + i * 4,
                          make_float4(t.x * inv, t.y * inv, t.z * inv, t.w * inv));
            }
        } else {
            uint2 z = make_uint2(0, 0);
#pragma unroll
            for (int i = 0; i < 8; i++) {
                int k = ko + i * 4;
                *(uint2*)(Ax + k * 2) = z;
                *(uint2*)(Ax + 128 + k * 2) = z;
                *(uint2*)(Ax + 256 + k * 2) = z;
                *(uint2*)(Atr + k * 2) = z;
                *(uint2*)(Atr + 128 + k * 2) = z;
                *(uint2*)(Atr + 256 + k * 2) = z;
            }
        }
    }
    __syncthreads();

    int lane = tid & 31, m0 = (tid >> 5) * 16;
    float c[8][4];
#pragma unroll
    for (int i = 0; i < 8; i++) c[i][0] = c[i][1] = c[i][2] = c[i][3] = 0.f;
    gemm_k192_acc(smem_u32(Axv), smem_u32(Bvv), m0, lane, c);
    gemm_k192_acc(smem_u32(At),  smem_u32(Bva), m0, lane, c);

    int r0 = m0 + (lane >> 2), r1 = r0 + 8;
    int col0 = (lane & 3) * 2;
    int n0 = nb + r0, n1 = nb + r1;
#pragma unroll
    for (int nt = 0; nt < 8; nt++) {
        int col = nt * 8 + col0;
        if (n0 < NN)
            *(float2*)(out_v + (size_t)n0 * 64 + col) =
                make_float2(c[nt][0] + sb[col], c[nt][1] + sb[col + 1]);
        if (n1 < NN)
            *(float2*)(out_v + (size_t)n1 * 64 + col) =
                make_float2(c[nt][2] + sb[col], c[nt][3] + sb[col + 1]);
    }
}

// ---------------------------------------------------------------------------
extern "C" void kernel_launch(void* const* d_in, const int* in_sizes, int n_in,
                              void* d_out, int out_size)
{
    const float* x_v   = (const float*)d_in[0];
    const float* x_a   = (const float*)d_in[1];
    const int*   arc   = (const int*)  d_in[2];
    const float* W_vv  = (const float*)d_in[3];
    const float* b_vv  = (const float*)d_in[4];
    const float* W_va  = (const float*)d_in[5];
    const float* W_att = (const float*)d_in[6];
    const float* b_att = (const float*)d_in[7];
    const float* W_aa  = (const float*)d_in[8];
    const float* b_aa  = (const float*)d_in[9];
    const float* W_av  = (const float*)d_in[10];

    float* out_v = (float*)d_out;
    float* out_a = (float*)d_out + (size_t)NN * 64;

    const int EDGE_SMEM = 62464;
    const int PRE_SMEM  = 77312;
    const int POST_SMEM = 153920;
    cudaFuncSetAttribute(edge_kernel, cudaFuncAttributeMaxDynamicSharedMemorySize, EDGE_SMEM);
    cudaFuncSetAttribute(node_pre_kernel, cudaFuncAttributeMaxDynamicSharedMemorySize, PRE_SMEM);
    cudaFuncSetAttribute(node_post_kernel, cudaFuncAttributeMaxDynamicSharedMemorySize, POST_SMEM);

    wprep_kernel<<<4, 256>>>(W_va, W_aa, W_av, W_vv);
    node_pre_kernel<<<(NN + 127) / 128, 256, PRE_SMEM>>>(x_v);
    edge_kernel<<<(NE + 127) / 128, 256, EDGE_SMEM>>>(x_a, arc, W_att, b_att,
                                                      b_aa, out_a);
    node_post_kernel<<<(NN + 127) / 128, 256, POST_SMEM>>>(x_v, b_vv, out_v);
}

// round 12
// speedup vs baseline: 1.4270x; 1.0957x over previous
#include <cuda_runtime.h>
#include <cuda_bf16.h>
#include <cstdint>

#define NN 50000
#define NE 1000000
#define SH 272            // [hi|lo] row stride in bytes (17x16B, odd -> conflict-free ldmatrix)
#define KW 128            // stored K extent (64 hi + 64 lo)

// ---------------- device scratch (allocation-free rule) ----------------
__device__ __align__(16) float g_P[NN * 64];     // x_v @ W_av^T
__device__ __align__(16) float g_T[NN * 64];     // sum_e w_e * x_a_e (input space)
__device__ __align__(16) float g_den[NN];
__device__ __align__(16) __nv_bfloat16 g_Wva_s[64 * KW];
__device__ __align__(16) __nv_bfloat16 g_Waa_s[64 * KW];
__device__ __align__(16) __nv_bfloat16 g_Wav_s[64 * KW];
__device__ __align__(16) __nv_bfloat16 g_Wvv_s[64 * KW];

// ---------------- helpers ----------------
__device__ __forceinline__ uint32_t smem_u32(const void* p) {
    uint32_t a;
    asm("{ .reg .u64 t; cvta.to.shared.u64 t, %1; cvt.u32.u64 %0, t; }"
        : "=r"(a) : "l"(p));
    return a;
}
__device__ __forceinline__ void ldm_x4(uint32_t* r, uint32_t addr) {
    asm volatile("ldmatrix.sync.aligned.m8n8.x4.shared.b16 {%0,%1,%2,%3}, [%4];"
                 : "=r"(r[0]), "=r"(r[1]), "=r"(r[2]), "=r"(r[3]) : "r"(addr));
}
__device__ __forceinline__ void mma16816(float* c, const uint32_t* a,
                                         uint32_t b0, uint32_t b1) {
    asm volatile(
        "mma.sync.aligned.m16n8k16.row.col.f32.bf16.bf16.f32 "
        "{%0,%1,%2,%3}, {%4,%5,%6,%7}, {%8,%9}, {%0,%1,%2,%3};"
        : "+f"(c[0]), "+f"(c[1]), "+f"(c[2]), "+f"(c[3])
        : "r"(a[0]), "r"(a[1]), "r"(a[2]), "r"(a[3]), "r"(b0), "r"(b1));
}
__device__ __forceinline__ uint32_t pack_bf2(__nv_bfloat16 a, __nv_bfloat16 b) {
    uint32_t ua = __bfloat16_as_ushort(a), ub = __bfloat16_as_ushort(b);
    return ua | (ub << 16);
}

// float4 -> [hi | lo] row (stride SH)
__device__ __forceinline__ void store_hl(char* Arow, int k, float4 f) {
    __nv_bfloat16 h0 = __float2bfloat16_rn(f.x), h1 = __float2bfloat16_rn(f.y);
    __nv_bfloat16 h2 = __float2bfloat16_rn(f.z), h3 = __float2bfloat16_rn(f.w);
    float l0 = f.x - __bfloat162float(h0), l1 = f.y - __bfloat162float(h1);
    float l2 = f.z - __bfloat162float(h2), l3 = f.w - __bfloat162float(h3);
    uint2 hv = make_uint2(pack_bf2(h0, h1), pack_bf2(h2, h3));
    uint2 lv = make_uint2(
        pack_bf2(__float2bfloat16_rn(l0), __float2bfloat16_rn(l1)),
        pack_bf2(__float2bfloat16_rn(l2), __float2bfloat16_rn(l3)));
    *(uint2*)(Arow + k * 2)       = hv;   // [0,64): hi
    *(uint2*)(Arow + 128 + k * 2) = lv;   // [64,128): lo
}

// GEMM core (ACCUMULATING): 16-row tile, A [hi|lo] @SH, B [hi|lo] @SH.
// Per kstep: a_hi, a_lo; per n-col: b_hi, b_lo; products hi*hi + lo*hi + hi*lo.
// 40 ldmatrix / 96 MMA per warp.
__device__ __forceinline__ void gemm_hl(uint32_t aB, uint32_t bB, int m0,
                                        int lane, float c[8][4]) {
    uint32_t aRow = aB + (uint32_t)(m0 + (lane & 15)) * SH + ((lane >> 4) << 4);
    uint32_t bRow = bB + (uint32_t)(lane & 15) * SH + ((lane >> 4) << 4);
#pragma unroll
    for (int ks = 0; ks < 4; ks++) {
        uint32_t ah[4], al[4];
        ldm_x4(ah, aRow + ks * 32);          // A hi cols
        ldm_x4(al, aRow + 128 + ks * 32);    // A lo cols
#pragma unroll
        for (int np = 0; np < 4; np++) {
            uint32_t bh[4], bl[4];
            ldm_x4(bh, bRow + np * 16 * SH + ks * 32);
            ldm_x4(bl, bRow + np * 16 * SH + 128 + ks * 32);
            mma16816(c[np * 2],     ah, bh[0], bh[2]);
            mma16816(c[np * 2 + 1], ah, bh[1], bh[3]);
            mma16816(c[np * 2],     al, bh[0], bh[2]);
            mma16816(c[np * 2 + 1], al, bh[1], bh[3]);
            mma16816(c[np * 2],     ah, bl[0], bl[2]);
            mma16816(c[np * 2 + 1], ah, bl[1], bl[3]);
        }
    }
}

// ---------------- wprep: weights -> [hi | lo] ----------------
__global__ void wprep_kernel(const float* __restrict__ Wva,
                             const float* __restrict__ Waa,
                             const float* __restrict__ Wav,
                             const float* __restrict__ Wvv) {
    const float* src[4] = {Wva, Waa, Wav, Wvv};
    __nv_bfloat16* dst[4] = {g_Wva_s, g_Waa_s, g_Wav_s, g_Wvv_s};
    int m = blockIdx.x;
    const float* W = src[m];
    __nv_bfloat16* D = dst[m];
    for (int i = threadIdx.x; i < 4096; i += 256) {
        int j = i >> 6, k = i & 63;
        float f = W[i];
        __nv_bfloat16 h = __float2bfloat16_rn(f);
        __nv_bfloat16 l = __float2bfloat16_rn(f - __bfloat162float(h));
        D[j * KW + k]      = h;
        D[j * KW + 64 + k] = l;
    }
}

// ---------------- K0: P = x_v @ W_av^T ; zero T, den ----------------
__global__ void __launch_bounds__(256, 3) node_pre_kernel(const float* __restrict__ x_v)
{
    extern __shared__ char sm[];
    char* A = sm;              // 128*272 = 34816
    char* B = sm + 34816;      // 64*272  = 17408
    int tid = threadIdx.x;
    int nb = blockIdx.x * 128;

    for (int i = tid; i < 1024; i += 256) {
        int r = i >> 4, c4 = i & 15;
        ((uint4*)(B + r * SH))[c4] = ((const uint4*)g_Wav_s)[i];
    }
    {
        int r = tid >> 1, ko = (tid & 1) * 32;
        int n = nb + r;
        char* Arow = A + r * SH;
        if (n < NN) {
            const float4* gx = (const float4*)(x_v + (size_t)n * 64 + ko);
#pragma unroll
            for (int i = 0; i < 8; i++) store_hl(Arow, ko + i * 4, gx[i]);
        } else {
            uint2 z = make_uint2(0, 0);
#pragma unroll
            for (int i = 0; i < 8; i++) {
                int k = ko + i * 4;
                *(uint2*)(Arow + k * 2) = z;
                *(uint2*)(Arow + 128 + k * 2) = z;
            }
        }
    }
    float4 z4 = make_float4(0.f, 0.f, 0.f, 0.f);
    for (int i = tid; i < 2048; i += 256) {
        int n = nb + (i >> 4);
        if (n < NN) ((float4*)(g_T + (size_t)n * 64))[i & 15] = z4;
    }
    if (tid < 128 && nb + tid < NN) g_den[nb + tid] = 0.f;
    __syncthreads();

    int lane = tid & 31, m0 = (tid >> 5) * 16;
    float c[8][4];
#pragma unroll
    for (int i = 0; i < 8; i++) c[i][0] = c[i][1] = c[i][2] = c[i][3] = 0.f;
    gemm_hl(smem_u32(A), smem_u32(B), m0, lane, c);

    int r0 = m0 + (lane >> 2), r1 = r0 + 8;
    int col0 = (lane & 3) * 2;
    int n0 = nb + r0, n1 = nb + r1;
#pragma unroll
    for (int nt = 0; nt < 8; nt++) {
        int col = nt * 8 + col0;
        if (n0 < NN) *(float2*)(g_P + (size_t)n0 * 64 + col) = make_float2(c[nt][0], c[nt][1]);
        if (n1 < NN) *(float2*)(g_P + (size_t)n1 * 64 + col) = make_float2(c[nt][2], c[nt][3]);
    }
}

// ---------------- K1: edge kernel ----------------
// smem: A 0..34816 | Baa ..52224 | slog | ssrc | sdst | sbias  (~54 KB, 3 CTAs/SM)
__global__ void __launch_bounds__(256, 3) edge_kernel(
    const float* __restrict__ x_a, const int* __restrict__ arc,
    const float* __restrict__ W_att, const float* __restrict__ b_att,
    const float* __restrict__ b_aa, float* __restrict__ out_a)
{
    extern __shared__ char sm[];
    char*  A    = sm;                       // 34816
    char*  Baa  = sm + 34816;               // 17408
    float* slog = (float*)(sm + 52224);     // 128
    int*   ssrc = (int*)(sm + 52736);       // 128
    int*   sdst = (int*)(sm + 53248);       // 128
    float* sbias= (float*)(sm + 53760);     // 64

    int tid = threadIdx.x;
    int eb = blockIdx.x * 128;

    // phase 1: weights -> smem; indices; bias; logit init
    for (int i = tid; i < 1024; i += 256) {
        int r = i >> 4, c4 = i & 15;
        ((uint4*)(Baa + r * SH))[c4] = ((const uint4*)g_Waa_s)[i];
    }
    float battv = __ldg(b_att);
    if (tid < 128) {
        int e = eb + tid;
        slog[tid] = (e < NE) ? battv : -1e30f;
        ssrc[tid] = (e < NE) ? __ldg(arc + e) : 0;
    } else {
        int r = tid - 128, e = eb + r;
        sdst[r] = (e < NE) ? __ldg(arc + NE + e) : 0;
        if (tid < 192) sbias[tid - 128] = __ldg(b_aa + (tid - 128));
    }
    __syncthreads();

    // phase 2: A tile convert + logit partial dot (2 threads per row)
    int r = tid >> 1, ko = (tid & 1) * 32;
    int er = eb + r;
    {
        char* Arow = A + r * SH;
        if (er < NE) {
            const float4* gx = (const float4*)(x_a + (size_t)er * 64 + ko);
            const float4* gw = (const float4*)(W_att + ko);
            float part = 0.f;
#pragma unroll
            for (int i = 0; i < 8; i++) {
                float4 f = gx[i];
                float4 wv = __ldg(gw + i);
                part += f.x * wv.x + f.y * wv.y + f.z * wv.z + f.w * wv.w;
                store_hl(Arow, ko + i * 4, f);
            }
            atomicAdd(&slog[r], part);
        } else {
            uint2 z = make_uint2(0, 0);
#pragma unroll
            for (int i = 0; i < 8; i++) {
                int k = ko + i * 4;
                *(uint2*)(Arow + k * 2) = z;
                *(uint2*)(Arow + 128 + k * 2) = z;
            }
        }
    }
    __syncthreads();

    // phase 3: w = exp(logit); den atomic
    if (tid < 128) {
        int e = eb + tid;
        float w = __expf(slog[tid]);
        slog[tid] = w;
        if (e < NE) atomicAdd(&g_den[sdst[tid]], w);
    }
    __syncthreads();

    // phase 4: scatter w * (hi+lo reconstructed x) into T[dst] (red.v4)
    if (er < NE) {
        float w = slog[r];
        float* Td = g_T + (size_t)sdst[r] * 64 + ko;
        const char* Arow = A + r * SH;
#pragma unroll
        for (int i = 0; i < 4; i++) {
            uint4 hv = *(const uint4*)(Arow + ko * 2 + i * 16);
            uint4 lv = *(const uint4*)(Arow + 128 + ko * 2 + i * 16);
            float2 f0h = __bfloat1622float2(*(__nv_bfloat162*)&hv.x);
            float2 f0l = __bfloat1622float2(*(__nv_bfloat162*)&lv.x);
            float2 f1h = __bfloat1622float2(*(__nv_bfloat162*)&hv.y);
            float2 f1l = __bfloat1622float2(*(__nv_bfloat162*)&lv.y);
            float2 f2h = __bfloat1622float2(*(__nv_bfloat162*)&hv.z);
            float2 f2l = __bfloat1622float2(*(__nv_bfloat162*)&lv.z);
            float2 f3h = __bfloat1622float2(*(__nv_bfloat162*)&hv.w);
            float2 f3l = __bfloat1622float2(*(__nv_bfloat162*)&lv.w);
            asm volatile("red.global.add.v4.f32 [%0], {%1,%2,%3,%4};"
                         :: "l"(Td + i * 8),
                            "f"((f0h.x + f0l.x) * w), "f"((f0h.y + f0l.y) * w),
                            "f"((f1h.x + f1l.x) * w), "f"((f1h.y + f1l.y) * w)
                         : "memory");
            asm volatile("red.global.add.v4.f32 [%0], {%1,%2,%3,%4};"
                         :: "l"(Td + i * 8 + 4),
                            "f"((f2h.x + f2l.x) * w), "f"((f2h.y + f2l.y) * w),
                            "f"((f3h.x + f3l.x) * w), "f"((f3h.y + f3l.y) * w)
                         : "memory");
        }
    }

    // phase 5: GEMM out_a = x_a @ W_aa^T + b_aa + P[src] + P[dst]
    int lane = tid & 31, m0 = (tid >> 5) * 16;
    float c[8][4];
#pragma unroll
    for (int i = 0; i < 8; i++) c[i][0] = c[i][1] = c[i][2] = c[i][3] = 0.f;
    gemm_hl(smem_u32(A), smem_u32(Baa), m0, lane, c);
    {
        int r0 = m0 + (lane >> 2), r1 = r0 + 8;
        int col0 = (lane & 3) * 2;
        int e0 = eb + r0, e1 = eb + r1;
        const float* Ps0 = g_P + (size_t)ssrc[r0] * 64;
        const float* Pd0 = g_P + (size_t)sdst[r0] * 64;
        const float* Ps1 = g_P + (size_t)ssrc[r1] * 64;
        const float* Pd1 = g_P + (size_t)sdst[r1] * 64;
#pragma unroll
        for (int nt = 0; nt < 8; nt++) {
            int col = nt * 8 + col0;
            if (e0 < NE) {
                float2 ps = *(const float2*)(Ps0 + col);
                float2 pd = *(const float2*)(Pd0 + col);
                *(float2*)(out_a + (size_t)e0 * 64 + col) =
                    make_float2(c[nt][0] + sbias[col] + ps.x + pd.x,
                                c[nt][1] + sbias[col + 1] + ps.y + pd.y);
            }
            if (e1 < NE) {
                float2 ps = *(const float2*)(Ps1 + col);
                float2 pd = *(const float2*)(Pd1 + col);
                *(float2*)(out_a + (size_t)e1 * 64 + col) =
                    make_float2(c[nt][2] + sbias[col] + ps.x + pd.x,
                                c[nt][3] + sbias[col + 1] + ps.y + pd.y);
            }
        }
    }
}

// ---------------- K2: h_v = x_v @ W_vv^T + b_vv + (T/den) @ W_va^T ----------------
__global__ void __launch_bounds__(256, 2) node_post_kernel(
    const float* __restrict__ x_v, const float* __restrict__ b_vv,
    float* __restrict__ out_v)
{
    extern __shared__ char sm[];
    char*  Axv = sm;                    // 34816
    char*  At  = sm + 34816;            // 34816
    char*  Bvv = sm + 69632;            // 17408
    char*  Bva = sm + 87040;            // 17408
    float* sb  = (float*)(sm + 104448); // 64
    int tid = threadIdx.x;
    int nb = blockIdx.x * 128;

    for (int i = tid; i < 1024; i += 256) {
        int r = i >> 4, c4 = i & 15;
        ((uint4*)(Bvv + r * SH))[c4] = ((const uint4*)g_Wvv_s)[i];
        ((uint4*)(Bva + r * SH))[c4] = ((const uint4*)g_Wva_s)[i];
    }
    if (tid < 64) sb[tid] = __ldg(b_vv + tid);
    {
        int r = tid >> 1, ko = (tid & 1) * 32;
        int n = nb + r;
        char* Ax = Axv + r * SH;
        char* Atr = At + r * SH;
        if (n < NN) {
            float d = g_den[n];
            float inv = (d > 0.f) ? 1.f / d : 0.f;
            const float4* gx = (const float4*)(x_v + (size_t)n * 64 + ko);
            const float4* gt = (const float4*)(g_T + (size_t)n * 64 + ko);
#pragma unroll
            for (int i = 0; i < 8; i++) {
                store_hl(Ax, ko + i * 4, gx[i]);
                float4 t = gt[i];
                store_hl(Atr, ko + i * 4,
                         make_float4(t.x * inv, t.y * inv, t.z * inv, t.w * inv));
            }
        } else {
            uint2 z = make_uint2(0, 0);
#pragma unroll
            for (int i = 0; i < 8; i++) {
                int k = ko + i * 4;
                *(uint2*)(Ax + k * 2) = z;
                *(uint2*)(Ax + 128 + k * 2) = z;
                *(uint2*)(Atr + k * 2) = z;
                *(uint2*)(Atr + 128 + k * 2) = z;
            }
        }
    }
    __syncthreads();

    int lane = tid & 31, m0 = (tid >> 5) * 16;
    float c[8][4];
#pragma unroll
    for (int i = 0; i < 8; i++) c[i][0] = c[i][1] = c[i][2] = c[i][3] = 0.f;
    gemm_hl(smem_u32(Axv), smem_u32(Bvv), m0, lane, c);
    gemm_hl(smem_u32(At),  smem_u32(Bva), m0, lane, c);

    int r0 = m0 + (lane >> 2), r1 = r0 + 8;
    int col0 = (lane & 3) * 2;
    int n0 = nb + r0, n1 = nb + r1;
#pragma unroll
    for (int nt = 0; nt < 8; nt++) {
        int col = nt * 8 + col0;
        if (n0 < NN)
            *(float2*)(out_v + (size_t)n0 * 64 + col) =
                make_float2(c[nt][0] + sb[col], c[nt][1] + sb[col + 1]);
        if (n1 < NN)
            *(float2*)(out_v + (size_t)n1 * 64 + col) =
                make_float2(c[nt][2] + sb[col], c[nt][3] + sb[col + 1]);
    }
}

// ---------------------------------------------------------------------------
extern "C" void kernel_launch(void* const* d_in, const int* in_sizes, int n_in,
                              void* d_out, int out_size)
{
    const float* x_v   = (const float*)d_in[0];
    const float* x_a   = (const float*)d_in[1];
    const int*   arc   = (const int*)  d_in[2];
    const float* W_vv  = (const float*)d_in[3];
    const float* b_vv  = (const float*)d_in[4];
    const float* W_va  = (const float*)d_in[5];
    const float* W_att = (const float*)d_in[6];
    const float* b_att = (const float*)d_in[7];
    const float* W_aa  = (const float*)d_in[8];
    const float* b_aa  = (const float*)d_in[9];
    const float* W_av  = (const float*)d_in[10];

    float* out_v = (float*)d_out;
    float* out_a = (float*)d_out + (size_t)NN * 64;

    const int EDGE_SMEM = 54016;
    const int PRE_SMEM  = 52224;
    const int POST_SMEM = 104704;
    cudaFuncSetAttribute(edge_kernel, cudaFuncAttributeMaxDynamicSharedMemorySize, EDGE_SMEM);
    cudaFuncSetAttribute(node_pre_kernel, cudaFuncAttributeMaxDynamicSharedMemorySize, PRE_SMEM);
    cudaFuncSetAttribute(node_post_kernel, cudaFuncAttributeMaxDynamicSharedMemorySize, POST_SMEM);

    wprep_kernel<<<4, 256>>>(W_va, W_aa, W_av, W_vv);
    node_pre_kernel<<<(NN + 127) / 128, 256, PRE_SMEM>>>(x_v);
    edge_kernel<<<(NE + 127) / 128, 256, EDGE_SMEM>>>(x_a, arc, W_att, b_att,
                                                      b_aa, out_a);
    node_post_kernel<<<(NN + 127) / 128, 256, POST_SMEM>>>(x_v, b_vv, out_v);
}

// round 14
// speedup vs baseline: 1.4392x; 1.0086x over previous
#include <cuda_runtime.h>
#include <cuda_bf16.h>
#include <cstdint>

#define NN 50000
#define NE 1000000
#define SH 272            // [hi|lo] row stride in bytes (17x16B, odd -> conflict-free ldmatrix)
#define KW 128            // stored K extent (64 hi + 64 lo)

// ---------------- device scratch (allocation-free rule) ----------------
__device__ __align__(16) float g_P[NN * 64];     // x_v @ W_av^T
__device__ __align__(16) float g_T[NN * 64];     // sum_e w_e * x_a_e (input space)
__device__ __align__(16) float g_den[NN];
__device__ __align__(16) __nv_bfloat16 g_Wva_s[64 * KW];
__device__ __align__(16) __nv_bfloat16 g_Waa_s[64 * KW];
__device__ __align__(16) __nv_bfloat16 g_Wav_s[64 * KW];
__device__ __align__(16) __nv_bfloat16 g_Wvv_s[64 * KW];

// ---------------- helpers ----------------
__device__ __forceinline__ uint32_t smem_u32(const void* p) {
    uint32_t a;
    asm("{ .reg .u64 t; cvta.to.shared.u64 t, %1; cvt.u32.u64 %0, t; }"
        : "=r"(a) : "l"(p));
    return a;
}
__device__ __forceinline__ void ldm_x4(uint32_t* r, uint32_t addr) {
    asm volatile("ldmatrix.sync.aligned.m8n8.x4.shared.b16 {%0,%1,%2,%3}, [%4];"
                 : "=r"(r[0]), "=r"(r[1]), "=r"(r[2]), "=r"(r[3]) : "r"(addr));
}
__device__ __forceinline__ void mma16816(float* c, const uint32_t* a,
                                         uint32_t b0, uint32_t b1) {
    asm volatile(
        "mma.sync.aligned.m16n8k16.row.col.f32.bf16.bf16.f32 "
        "{%0,%1,%2,%3}, {%4,%5,%6,%7}, {%8,%9}, {%0,%1,%2,%3};"
        : "+f"(c[0]), "+f"(c[1]), "+f"(c[2]), "+f"(c[3])
        : "r"(a[0]), "r"(a[1]), "r"(a[2]), "r"(a[3]), "r"(b0), "r"(b1));
}

// float4 -> [hi | lo] row (stride SH), packed bf16x2 converts
__device__ __forceinline__ void store_hl(char* Arow, int k, float4 f) {
    __nv_bfloat162 h01 = __floats2bfloat162_rn(f.x, f.y);
    __nv_bfloat162 h23 = __floats2bfloat162_rn(f.z, f.w);
    float2 a01 = __bfloat1622float2(h01);
    float2 a23 = __bfloat1622float2(h23);
    __nv_bfloat162 l01 = __floats2bfloat162_rn(f.x - a01.x, f.y - a01.y);
    __nv_bfloat162 l23 = __floats2bfloat162_rn(f.z - a23.x, f.w - a23.y);
    uint2 hv = make_uint2(*(uint32_t*)&h01, *(uint32_t*)&h23);
    uint2 lv = make_uint2(*(uint32_t*)&l01, *(uint32_t*)&l23);
    *(uint2*)(Arow + k * 2)       = hv;   // [0,64): hi
    *(uint2*)(Arow + 128 + k * 2) = lv;   // [64,128): lo
}

// GEMM core (ACCUMULATING): 16-row tile, A [hi|lo] @SH, B [hi|lo] @SH.
// Products hi*hi + lo*hi + hi*lo.  40 ldmatrix / 96 MMA per warp.
__device__ __forceinline__ void gemm_hl(uint32_t aB, uint32_t bB, int m0,
                                        int lane, float c[8][4]) {
    uint32_t aRow = aB + (uint32_t)(m0 + (lane & 15)) * SH + ((lane >> 4) << 4);
    uint32_t bRow = bB + (uint32_t)(lane & 15) * SH + ((lane >> 4) << 4);
#pragma unroll
    for (int ks = 0; ks < 4; ks++) {
        uint32_t ah[4], al[4];
        ldm_x4(ah, aRow + ks * 32);          // A hi cols
        ldm_x4(al, aRow + 128 + ks * 32);    // A lo cols
#pragma unroll
        for (int np = 0; np < 4; np++) {
            uint32_t bh[4], bl[4];
            ldm_x4(bh, bRow + np * 16 * SH + ks * 32);
            ldm_x4(bl, bRow + np * 16 * SH + 128 + ks * 32);
            mma16816(c[np * 2],     ah, bh[0], bh[2]);
            mma16816(c[np * 2 + 1], ah, bh[1], bh[3]);
            mma16816(c[np * 2],     al, bh[0], bh[2]);
            mma16816(c[np * 2 + 1], al, bh[1], bh[3]);
            mma16816(c[np * 2],     ah, bl[0], bl[2]);
            mma16816(c[np * 2 + 1], ah, bl[1], bl[3]);
        }
    }
}

// ---------------- wprep: weights -> [hi | lo] ----------------
__global__ void wprep_kernel(const float* __restrict__ Wva,
                             const float* __restrict__ Waa,
                             const float* __restrict__ Wav,
                             const float* __restrict__ Wvv) {
    const float* src[4] = {Wva, Waa, Wav, Wvv};
    __nv_bfloat16* dst[4] = {g_Wva_s, g_Waa_s, g_Wav_s, g_Wvv_s};
    int m = blockIdx.x;
    const float* W = src[m];
    __nv_bfloat16* D = dst[m];
    for (int i = threadIdx.x; i < 4096; i += 256) {
        int j = i >> 6, k = i & 63;
        float f = W[i];
        __nv_bfloat16 h = __float2bfloat16_rn(f);
        __nv_bfloat16 l = __float2bfloat16_rn(f - __bfloat162float(h));
        D[j * KW + k]      = h;
        D[j * KW + 64 + k] = l;
    }
}

// ---------------- K0: P = x_v @ W_av^T ; zero T, den ----------------
__global__ void __launch_bounds__(256, 3) node_pre_kernel(const float* __restrict__ x_v)
{
    extern __shared__ char sm[];
    char* A = sm;              // 128*272 = 34816
    char* B = sm + 34816;      // 64*272  = 17408
    int tid = threadIdx.x;
    int nb = blockIdx.x * 128;

    for (int i = tid; i < 1024; i += 256) {
        int r = i >> 4, c4 = i & 15;
        ((uint4*)(B + r * SH))[c4] = ((const uint4*)g_Wav_s)[i];
    }
    {
        int r = tid >> 1, ko = (tid & 1) * 32;
        int n = nb + r;
        char* Arow = A + r * SH;
        if (n < NN) {
            const float4* gx = (const float4*)(x_v + (size_t)n * 64 + ko);
#pragma unroll
            for (int i = 0; i < 8; i++) store_hl(Arow, ko + i * 4, gx[i]);
        } else {
            uint2 z = make_uint2(0, 0);
#pragma unroll
            for (int i = 0; i < 8; i++) {
                int k = ko + i * 4;
                *(uint2*)(Arow + k * 2) = z;
                *(uint2*)(Arow + 128 + k * 2) = z;
            }
        }
    }
    float4 z4 = make_float4(0.f, 0.f, 0.f, 0.f);
    for (int i = tid; i < 2048; i += 256) {
        int n = nb + (i >> 4);
        if (n < NN) ((float4*)(g_T + (size_t)n * 64))[i & 15] = z4;
    }
    if (tid < 128 && nb + tid < NN) g_den[nb + tid] = 0.f;
    __syncthreads();

    int lane = tid & 31, m0 = (tid >> 5) * 16;
    float c[8][4];
#pragma unroll
    for (int i = 0; i < 8; i++) c[i][0] = c[i][1] = c[i][2] = c[i][3] = 0.f;
    gemm_hl(smem_u32(A), smem_u32(B), m0, lane, c);

    int r0 = m0 + (lane >> 2), r1 = r0 + 8;
    int col0 = (lane & 3) * 2;
    int n0 = nb + r0, n1 = nb + r1;
#pragma unroll
    for (int nt = 0; nt < 8; nt++) {
        int col = nt * 8 + col0;
        if (n0 < NN) *(float2*)(g_P + (size_t)n0 * 64 + col) = make_float2(c[nt][0], c[nt][1]);
        if (n1 < NN) *(float2*)(g_P + (size_t)n1 * 64 + col) = make_float2(c[nt][2], c[nt][3]);
    }
}

// ---------------- K1: edge kernel — 2-barrier pipeline ----------------
// smem: A 0..34816 | Baa ..52224 | ssrc @52224 | sdst @52736 | sbias @53248
__global__ void __launch_bounds__(256, 3) edge_kernel(
    const float* __restrict__ x_a, const int* __restrict__ arc,
    const float* __restrict__ W_att, const float* __restrict__ b_att,
    const float* __restrict__ b_aa, float* __restrict__ out_a)
{
    extern __shared__ char sm[];
    char*  A    = sm;                       // 34816
    char*  Baa  = sm + 34816;               // 17408
    int*   ssrc = (int*)(sm + 52224);       // 128
    int*   sdst = (int*)(sm + 52736);       // 128
    float* sbias= (float*)(sm + 53248);     // 64

    int tid = threadIdx.x;
    int eb = blockIdx.x * 128;
    float battv = __ldg(b_att);

    // phase 1: weights -> smem; indices; bias
    for (int i = tid; i < 1024; i += 256) {
        int r = i >> 4, c4 = i & 15;
        ((uint4*)(Baa + r * SH))[c4] = ((const uint4*)g_Waa_s)[i];
    }
    if (tid < 128) {
        int e = eb + tid;
        ssrc[tid] = (e < NE) ? __ldg(arc + e) : 0;
    } else {
        int r = tid - 128, e = eb + r;
        sdst[r] = (e < NE) ? __ldg(arc + NE + e) : 0;
        if (tid < 192) sbias[tid - 128] = __ldg(b_aa + (tid - 128));
    }
    __syncthreads();

    // phase 2 (merged): load+convert A, logit via shfl, exp, den atomic, scatter
    {
        int r = tid >> 1, ko = (tid & 1) * 32;
        int er = eb + r;
        char* Arow = A + r * SH;
        float4 xf[8];
        float part = 0.f;
        if (er < NE) {
            const float4* gx = (const float4*)(x_a + (size_t)er * 64 + ko);
            const float4* gw = (const float4*)(W_att + ko);
#pragma unroll
            for (int i = 0; i < 8; i++) {
                float4 f = gx[i];
                xf[i] = f;
                float4 wv = __ldg(gw + i);
                part += f.x * wv.x + f.y * wv.y + f.z * wv.z + f.w * wv.w;
                store_hl(Arow, ko + i * 4, f);
            }
        } else {
            uint2 z = make_uint2(0, 0);
#pragma unroll
            for (int i = 0; i < 8; i++) {
                int k = ko + i * 4;
                *(uint2*)(Arow + k * 2) = z;
                *(uint2*)(Arow + 128 + k * 2) = z;
            }
        }
        // pair threads (tid, tid^1) share one edge row
        float tot = part + __shfl_xor_sync(0xffffffffu, part, 1);
        if (er < NE) {
            float w = __expf(tot + battv);
            int dst = sdst[r];
            if ((tid & 1) == 0) atomicAdd(&g_den[dst], w);
            float* Td = g_T + (size_t)dst * 64 + ko;
#pragma unroll
            for (int i = 0; i < 8; i++) {
                float4 f = xf[i];
                asm volatile("red.global.add.v4.f32 [%0], {%1,%2,%3,%4};"
                             :: "l"(Td + i * 4),
                                "f"(f.x * w), "f"(f.y * w), "f"(f.z * w), "f"(f.w * w)
                             : "memory");
            }
        }
    }
    __syncthreads();

    // phase 3: GEMM out_a = x_a @ W_aa^T + b_aa + P[src] + P[dst]
    int lane = tid & 31, m0 = (tid >> 5) * 16;
    float c[8][4];
#pragma unroll
    for (int i = 0; i < 8; i++) c[i][0] = c[i][1] = c[i][2] = c[i][3] = 0.f;
    gemm_hl(smem_u32(A), smem_u32(Baa), m0, lane, c);
    {
        int r0 = m0 + (lane >> 2), r1 = r0 + 8;
        int col0 = (lane & 3) * 2;
        int e0 = eb + r0, e1 = eb + r1;
        const float* Ps0 = g_P + (size_t)ssrc[r0] * 64;
        const float* Pd0 = g_P + (size_t)sdst[r0] * 64;
        const float* Ps1 = g_P + (size_t)ssrc[r1] * 64;
        const float* Pd1 = g_P + (size_t)sdst[r1] * 64;
#pragma unroll
        for (int nt = 0; nt < 8; nt++) {
            int col = nt * 8 + col0;
            if (e0 < NE) {
                float2 ps = *(const float2*)(Ps0 + col);
                float2 pd = *(const float2*)(Pd0 + col);
                *(float2*)(out_a + (size_t)e0 * 64 + col) =
                    make_float2(c[nt][0] + sbias[col] + ps.x + pd.x,
                                c[nt][1] + sbias[col + 1] + ps.y + pd.y);
            }
            if (e1 < NE) {
                float2 ps = *(const float2*)(Ps1 + col);
                float2 pd = *(const float2*)(Pd1 + col);
                *(float2*)(out_a + (size_t)e1 * 64 + col) =
                    make_float2(c[nt][2] + sbias[col] + ps.x + pd.x,
                                c[nt][3] + sbias[col + 1] + ps.y + pd.y);
            }
        }
    }
}

// ---------------- K2: h_v = x_v @ W_vv^T + b_vv + (T/den) @ W_va^T ----------------
__global__ void __launch_bounds__(256, 2) node_post_kernel(
    const float* __restrict__ x_v, const float* __restrict__ b_vv,
    float* __restrict__ out_v)
{
    extern __shared__ char sm[];
    char*  Axv = sm;                    // 34816
    char*  At  = sm + 34816;            // 34816
    char*  Bvv = sm + 69632;            // 17408
    char*  Bva = sm + 87040;            // 17408
    float* sb  = (float*)(sm + 104448); // 64
    int tid = threadIdx.x;
    int nb = blockIdx.x * 128;

    for (int i = tid; i < 1024; i += 256) {
        int r = i >> 4, c4 = i & 15;
        ((uint4*)(Bvv + r * SH))[c4] = ((const uint4*)g_Wvv_s)[i];
        ((uint4*)(Bva + r * SH))[c4] = ((const uint4*)g_Wva_s)[i];
    }
    if (tid < 64) sb[tid] = __ldg(b_vv + tid);
    {
        int r = tid >> 1, ko = (tid & 1) * 32;
        int n = nb + r;
        char* Ax = Axv + r * SH;
        char* Atr = At + r * SH;
        if (n < NN) {
            float d = g_den[n];
            float inv = (d > 0.f) ? 1.f / d : 0.f;
            const float4* gx = (const float4*)(x_v + (size_t)n * 64 + ko);
            const float4* gt = (const float4*)(g_T + (size_t)n * 64 + ko);
#pragma unroll
            for (int i = 0; i < 8; i++) {
                store_hl(Ax, ko + i * 4, gx[i]);
                float4 t = gt[i];
                store_hl(Atr, ko + i * 4,
                         make_float4(t.x * inv, t.y * inv, t.z * inv, t.w * inv));
            }
        } else {
            uint2 z = make_uint2(0, 0);
#pragma unroll
            for (int i = 0; i < 8; i++) {
                int k = ko + i * 4;
                *(uint2*)(Ax + k * 2) = z;
                *(uint2*)(Ax + 128 + k * 2) = z;
                *(uint2*)(Atr + k * 2) = z;
                *(uint2*)(Atr + 128 + k * 2) = z;
            }
        }
    }
    __syncthreads();

    int lane = tid & 31, m0 = (tid >> 5) * 16;
    float c[8][4];
#pragma unroll
    for (int i = 0; i < 8; i++) c[i][0] = c[i][1] = c[i][2] = c[i][3] = 0.f;
    gemm_hl(smem_u32(Axv), smem_u32(Bvv), m0, lane, c);
    gemm_hl(smem_u32(At),  smem_u32(Bva), m0, lane, c);

    int r0 = m0 + (lane >> 2), r1 = r0 + 8;
    int col0 = (lane & 3) * 2;
    int n0 = nb + r0, n1 = nb + r1;
#pragma unroll
    for (int nt = 0; nt < 8; nt++) {
        int col = nt * 8 + col0;
        if (n0 < NN)
            *(float2*)(out_v + (size_t)n0 * 64 + col) =
                make_float2(c[nt][0] + sb[col], c[nt][1] + sb[col + 1]);
        if (n1 < NN)
            *(float2*)(out_v + (size_t)n1 * 64 + col) =
                make_float2(c[nt][2] + sb[col], c[nt][3] + sb[col + 1]);
    }
}

// ---------------------------------------------------------------------------
extern "C" void kernel_launch(void* const* d_in, const int* in_sizes, int n_in,
                              void* d_out, int out_size)
{
    const float* x_v   = (const float*)d_in[0];
    const float* x_a   = (const float*)d_in[1];
    const int*   arc   = (const int*)  d_in[2];
    const float* W_vv  = (const float*)d_in[3];
    const float* b_vv  = (const float*)d_in[4];
    const float* W_va  = (const float*)d_in[5];
    const float* W_att = (const float*)d_in[6];
    const float* b_att = (const float*)d_in[7];
    const float* W_aa  = (const float*)d_in[8];
    const float* b_aa  = (const float*)d_in[9];
    const float* W_av  = (const float*)d_in[10];

    float* out_v = (float*)d_out;
    float* out_a = (float*)d_out + (size_t)NN * 64;

    const int EDGE_SMEM = 53504;
    const int PRE_SMEM  = 52224;
    const int POST_SMEM = 104704;
    cudaFuncSetAttribute(edge_kernel, cudaFuncAttributeMaxDynamicSharedMemorySize, EDGE_SMEM);
    cudaFuncSetAttribute(node_pre_kernel, cudaFuncAttributeMaxDynamicSharedMemorySize, PRE_SMEM);
    cudaFuncSetAttribute(node_post_kernel, cudaFuncAttributeMaxDynamicSharedMemorySize, POST_SMEM);

    wprep_kernel<<<4, 256>>>(W_va, W_aa, W_av, W_vv);
    node_pre_kernel<<<(NN + 127) / 128, 256, PRE_SMEM>>>(x_v);
    edge_kernel<<<(NE + 127) / 128, 256, EDGE_SMEM>>>(x_a, arc, W_att, b_att,
                                                      b_aa, out_a);
    node_post_kernel<<<(NN + 127) / 128, 256, POST_SMEM>>>(x_v, b_vv, out_v);
}